// round 15
// baseline (speedup 1.0000x reference)
#include <cuda_runtime.h>
#include <math.h>

#define BATCH 1024
typedef unsigned long long u64;

// ---------------- f32x2 packed-math helpers (sm_100+) ------------------------
__device__ __forceinline__ u64 splat2(float v) {
    u64 r;
    asm("mov.b64 %0, {%1, %1};" : "=l"(r) : "f"(v));
    return r;
}
__device__ __forceinline__ void fma2(u64& d, u64 a, u64 b) {
    asm("fma.rn.f32x2 %0, %1, %2, %0;" : "+l"(d) : "l"(a), "l"(b));
}
__device__ __forceinline__ float2 unpack2(u64 v) {
    float2 f;
    asm("mov.b64 {%0, %1}, %2;" : "=f"(f.x), "=f"(f.y) : "l"(v));
    return f;
}

// ---------------- device scratch (allocation-free rule: __device__ globals) --
__device__ float g_h1[(size_t)1024*32*32*32];   // conv1 raw out
__device__ float g_h2[(size_t)1024*64*32*32];   // conv2 raw out
__device__ float g_AS[(size_t)1024*64*16*16];   // conv3 raw out
__device__ float g_S1[(size_t)1024*192*16*16];  // convS1 raw out
__device__ float g_S2[(size_t)1024*192*8*8];    // convS2 raw out
__device__ float g_Araw[(size_t)1024*64*16*16]; // convA raw out

__device__ float g_sum[640];
__device__ float g_sq[640];
__device__ float g_scale[640];
__device__ float g_shift[640];
__device__ float g_loss[4];     // [0]=l1 sum, [1]=l2 sum, [2]=l3 sum

// stage channel offsets into stat arrays
#define O0 0     // 32 ch (conv1)
#define O1 32    // 64 ch (conv2)
#define O2 96    // 64 ch (conv3)
#define O3 160   // 64 ch (convA)
#define O4 224   // 192 ch (convS1)
#define O5 416   // 192 ch (convS2)

// ----------------------------------------------------------------------------
__global__ void zero_kernel(float* sum, float* sq, float* loss) {
    int i = blockIdx.x * blockDim.x + threadIdx.x;
    if (i < 608) { sum[i] = 0.f; sq[i] = 0.f; }
    if (i < 3) loss[i] = 0.f;
}

__device__ __forceinline__ void atomic_block_sum(float v, float* dst) {
    __shared__ float red[32];
    int lane = threadIdx.x & 31, warp = threadIdx.x >> 5;
#pragma unroll
    for (int o = 16; o > 0; o >>= 1) v += __shfl_xor_sync(0xffffffffu, v, o);
    if (lane == 0) red[warp] = v;
    __syncthreads();
    if (warp == 0) {
        int nw = (blockDim.x + 31) >> 5;
        float s = (lane < nw) ? red[lane] : 0.f;
#pragma unroll
        for (int o = 16; o > 0; o >>= 1) s += __shfl_xor_sync(0xffffffffu, s, o);
        if (lane == 0) atomicAdd(dst, s);
    }
}

// ----------------------------------------------------------------------------
// Direct 3x3 conv, pad=1, stride 1 or 2.  v5: 128-thread blocks, 4 blocks/SM,
// CPT output channels per thread (f32x2-packed pairs), PXPT consecutive x
// pixels per thread fed by aligned float4 windows per (c,ky), YSPLIT row
// splitting.  Generalized stats epilogue supports channel-sub groups smaller
// than a warp (SPAN = min(NPT,32)).  Row-based coalesced slab loader with
// producer BN+ReLU on load.  grid = (batch, COUT/COUTG, YSPLIT), 128 threads.
// ----------------------------------------------------------------------------
template<int CIN, int CSLAB, int HIN, int WIN, int STRIDE, int CPT, int PXPT,
         int YSPLIT, bool HASBN>
__global__ __launch_bounds__(128, 4)
void conv3x3_v5(const float* __restrict__ in, int cin_tot, int cin_off,
                const float* __restrict__ bscale, const float* __restrict__ bshift,
                const float* __restrict__ w, int cout_tot,
                float* __restrict__ out,
                float* __restrict__ chsum, float* __restrict__ chsq, int ch_off)
{
    constexpr int TPB    = 128;
    constexpr int HOUT   = (STRIDE == 1) ? HIN : HIN / 2;
    constexpr int WOUT   = (STRIDE == 1) ? WIN : WIN / 2;
    constexpr int HOB    = HOUT / YSPLIT;          // output rows per block
    constexpr int TPR    = WOUT / PXPT;            // threads per output row
    constexpr int NPT    = HOB * TPR;              // pixel-thread count
    constexpr int CSPLIT = TPB / NPT;              // channel groups of threads
    constexpr int COUTG  = CPT * CSPLIT;           // out channels per block
    constexpr int HSLAB  = (HOB - 1) * STRIDE + 3;
    constexpr int WP     = ((WIN + 2 + 3) / 4) * 4;  // padded row, 16B aligned
    constexpr int NSLAB  = CIN / CSLAB;
    constexpr int IW     = (PXPT - 1) * STRIDE + 3;  // input window width
    constexpr int NV4    = (IW + 3) / 4;             // float4 loads per window
    constexpr int NPAIR  = CPT / 2;
    constexpr int NPIX   = HOUT * WOUT;
    constexpr int SPAN   = (NPT < 32) ? NPT : 32;    // reduce span (lanes)
    constexpr int NGRP   = TPB / SPAN;               // reduce groups
    constexpr int GPC    = NGRP / CSPLIT;            // groups per channel-sub

    extern __shared__ float sm[];
    float* s_in = sm;                         // CSLAB * HSLAB * WP
    float* s_w  = sm + CSLAB * HSLAB * WP;    // [c][tap][COUTG]
    __shared__ float s_red[NGRP][2 * CPT];

    const int b    = blockIdx.x;
    const int cog  = blockIdx.y * COUTG;
    const int oy0  = blockIdx.z * HOB;
    const int t    = threadIdx.x;
    const int pt   = t % NPT;
    const int csub = t / NPT;
    const int row  = pt / TPR;                // block-local output row
    const int x0   = (pt % TPR) * PXPT;       // first output col
    const int ib   = x0 * STRIDE;             // slab col of kx=0 (4-aligned)
    const int gy0  = oy0 * STRIDE - 1;        // input row of slab row 0

    u64 acc[NPAIR][PXPT];
#pragma unroll
    for (int i = 0; i < NPAIR; ++i)
#pragma unroll
        for (int p = 0; p < PXPT; ++p) acc[i][p] = 0ull;

    for (int sl = 0; sl < NSLAB; ++sl) {
        const int cbase = sl * CSLAB;
        __syncthreads();
        // ---- input slab: one thread = one (c,y) row; coalesced float4 ----
        for (int ridx = t; ridx < CSLAB * HSLAB; ridx += TPB) {
            const int c  = ridx / HSLAB;
            const int y  = ridx - c * HSLAB;
            const int gy = gy0 + y;
            float* dst = s_in + ridx * WP;
            if ((unsigned)gy >= (unsigned)HIN) {
#pragma unroll
                for (int j = 0; j < WP; ++j) dst[j] = 0.f;
            } else {
                const int gc = cin_off + cbase + c;
                const float4* src = reinterpret_cast<const float4*>(
                    in + (((long)(b * cin_tot + gc)) * HIN + gy) * WIN);
                dst[0] = 0.f;
#pragma unroll
                for (int j = WIN + 1; j < WP; ++j) dst[j] = 0.f;
                if (HASBN) {
                    const float sc = bscale[gc], sh = bshift[gc];
#pragma unroll
                    for (int j = 0; j < WIN / 4; ++j) {
                        float4 v = src[j];
                        dst[1 + 4*j + 0] = fmaxf(fmaf(v.x, sc, sh), 0.f);
                        dst[1 + 4*j + 1] = fmaxf(fmaf(v.y, sc, sh), 0.f);
                        dst[1 + 4*j + 2] = fmaxf(fmaf(v.z, sc, sh), 0.f);
                        dst[1 + 4*j + 3] = fmaxf(fmaf(v.w, sc, sh), 0.f);
                    }
                } else {
#pragma unroll
                    for (int j = 0; j < WIN / 4; ++j) {
                        float4 v = src[j];
                        dst[1 + 4*j + 0] = v.x;
                        dst[1 + 4*j + 1] = v.y;
                        dst[1 + 4*j + 2] = v.z;
                        dst[1 + 4*j + 3] = v.w;
                    }
                }
            }
        }
        // ---- weights: s_w[(c*9+tap)*COUTG + co] ----
        for (int idx = t; idx < CSLAB * 9 * COUTG; idx += TPB) {
            int co  = idx % COUTG;
            int r   = idx / COUTG;
            int tap = r % 9;
            int c   = r / 9;
            s_w[idx] = w[((long)(cog + co) * CIN + cbase + c) * 9 + tap];
        }
        __syncthreads();
        // ---- compute (unroll 2 across channels for latency overlap) ----
#pragma unroll 2
        for (int c = 0; c < CSLAB; ++c) {
            const float* si = s_in + (c * HSLAB + row * STRIDE) * WP + ib;
#pragma unroll
            for (int ky = 0; ky < 3; ++ky) {
                float4 v4[NV4];
                const float4* rp = reinterpret_cast<const float4*>(si + ky * WP);
#pragma unroll
                for (int j = 0; j < NV4; ++j) v4[j] = rp[j];
                const float* vf = reinterpret_cast<const float*>(v4);
                u64 iv[IW];
#pragma unroll
                for (int d = 0; d < IW; ++d) iv[d] = splat2(vf[d]);
#pragma unroll
                for (int kx = 0; kx < 3; ++kx) {
                    const ulonglong2* wr = reinterpret_cast<const ulonglong2*>(
                        s_w + (c * 9 + ky * 3 + kx) * COUTG + csub * CPT);
#pragma unroll
                    for (int q = 0; q < CPT / 4; ++q) {
                        ulonglong2 wp = wr[q];
#pragma unroll
                        for (int p = 0; p < PXPT; ++p) {
                            fma2(acc[2*q  ][p], wp.x, iv[p * STRIDE + kx]);
                            fma2(acc[2*q+1][p], wp.y, iv[p * STRIDE + kx]);
                        }
                    }
                }
            }
        }
    }

    // ---- epilogue: vectorized raw out + per-channel stats ----
    const int lane = t & 31;
    const int grp  = t / SPAN;
    const long obase = ((long)b * cout_tot + cog + csub * CPT) * NPIX
                       + (oy0 + row) * WOUT + x0;
#pragma unroll
    for (int pr = 0; pr < NPAIR; ++pr) {
        float vx[PXPT], vy[PXPT];
        float psA = 0.f, pqA = 0.f, psB = 0.f, pqB = 0.f;
#pragma unroll
        for (int p = 0; p < PXPT; ++p) {
            float2 v = unpack2(acc[pr][p]);
            vx[p] = v.x; vy[p] = v.y;
            psA += v.x; pqA += v.x * v.x;
            psB += v.y; pqB += v.y * v.y;
        }
        if constexpr (PXPT == 4) {
            *reinterpret_cast<float4*>(out + obase + (long)(2*pr) * NPIX) =
                make_float4(vx[0], vx[1], vx[2], vx[3]);
            *reinterpret_cast<float4*>(out + obase + (long)(2*pr+1) * NPIX) =
                make_float4(vy[0], vy[1], vy[2], vy[3]);
        } else {
            *reinterpret_cast<float2*>(out + obase + (long)(2*pr) * NPIX) =
                make_float2(vx[0], vx[1]);
            *reinterpret_cast<float2*>(out + obase + (long)(2*pr+1) * NPIX) =
                make_float2(vy[0], vy[1]);
        }
#pragma unroll
        for (int o = SPAN / 2; o > 0; o >>= 1) {
            psA += __shfl_xor_sync(0xffffffffu, psA, o);
            pqA += __shfl_xor_sync(0xffffffffu, pqA, o);
            psB += __shfl_xor_sync(0xffffffffu, psB, o);
            pqB += __shfl_xor_sync(0xffffffffu, pqB, o);
        }
        if ((lane % SPAN) == 0) {
            s_red[grp][4*pr]   = psA; s_red[grp][4*pr+1] = pqA;
            s_red[grp][4*pr+2] = psB; s_red[grp][4*pr+3] = pqB;
        }
    }
    __syncthreads();
    if (t < COUTG) {
        const int sub = t / CPT, co = t % CPT;
        float ps = 0.f, pq = 0.f;
#pragma unroll
        for (int gi = 0; gi < GPC; ++gi) {
            ps += s_red[sub * GPC + gi][2*co];
            pq += s_red[sub * GPC + gi][2*co+1];
        }
        atomicAdd(&chsum[ch_off + cog + t], ps);
        atomicAdd(&chsq [ch_off + cog + t], pq);
    }
}

// ----------------------------------------------------------------------------
// 1x1 conv (A head): AS[:, :32] -> 64 channels over 16x16, f32x2 packed
// ----------------------------------------------------------------------------
__global__ __launch_bounds__(256)
void conv1x1_bn(const float* __restrict__ in, const float* __restrict__ bscale,
                const float* __restrict__ bshift, const float* __restrict__ w,
                float* __restrict__ out,
                float* __restrict__ chsum, float* __restrict__ chsq, int ch_off)
{
    __shared__ __align__(16) float s_in[32 * 256];
    __shared__ __align__(16) float s_w[32 * 64];
    __shared__ float s_red[8][128];
    const int b = blockIdx.x, t = threadIdx.x;

    for (int idx = t; idx < 32 * 256; idx += 256) {
        int ci = idx >> 8, p = idx & 255;
        float v = in[((long)(b * 64 + ci)) * 256 + p];
        s_in[idx] = fmaxf(fmaf(v, bscale[ci], bshift[ci]), 0.f);
    }
    for (int idx = t; idx < 32 * 64; idx += 256) {
        int ci = idx >> 6, co = idx & 63;
        s_w[idx] = w[co * 32 + ci];
    }
    __syncthreads();

    u64 acc[32];
#pragma unroll
    for (int i = 0; i < 32; ++i) acc[i] = 0ull;

    for (int ci = 0; ci < 32; ++ci) {
        u64 vp = splat2(s_in[ci * 256 + t]);
        const ulonglong2* wr = reinterpret_cast<const ulonglong2*>(s_w + ci * 64);
#pragma unroll
        for (int q = 0; q < 16; ++q) {
            ulonglong2 wp = wr[q];
            fma2(acc[2*q  ], wp.x, vp);
            fma2(acc[2*q+1], wp.y, vp);
        }
    }

    const int lane = t & 31, warp = t >> 5;
#pragma unroll
    for (int p = 0; p < 32; ++p) {
        float2 v = unpack2(acc[p]);
        out[((long)(b * 64 + 2*p    )) * 256 + t] = v.x;
        out[((long)(b * 64 + 2*p + 1)) * 256 + t] = v.y;
        float psA = v.x, pqA = v.x * v.x, psB = v.y, pqB = v.y * v.y;
#pragma unroll
        for (int o = 16; o > 0; o >>= 1) {
            psA += __shfl_xor_sync(0xffffffffu, psA, o);
            pqA += __shfl_xor_sync(0xffffffffu, pqA, o);
            psB += __shfl_xor_sync(0xffffffffu, psB, o);
            pqB += __shfl_xor_sync(0xffffffffu, pqB, o);
        }
        if (lane == 0) {
            s_red[warp][4*p]   = psA; s_red[warp][4*p+1] = pqA;
            s_red[warp][4*p+2] = psB; s_red[warp][4*p+3] = pqB;
        }
    }
    __syncthreads();
    if (t < 64) {
        float ps = 0.f, pq = 0.f;
#pragma unroll
        for (int wi = 0; wi < 8; ++wi) { ps += s_red[wi][2*t]; pq += s_red[wi][2*t+1]; }
        atomicAdd(&chsum[ch_off + t], ps);
        atomicAdd(&chsq [ch_off + t], pq);
    }
}

// ----------------------------------------------------------------------------
__global__ void bn_finalize(const float* __restrict__ sum, const float* __restrict__ sq,
                            const float* __restrict__ g, const float* __restrict__ bb,
                            float* __restrict__ scale, float* __restrict__ shift,
                            float inv_n, int off, int C)
{
    int c = threadIdx.x;
    if (c >= C) return;
    float m   = sum[off + c] * inv_n;
    float var = sq[off + c] * inv_n - m * m;
    float s   = g[c] * rsqrtf(var + 1e-5f);
    scale[off + c] = s;
    shift[off + c] = bb[c] - m * s;
}

// ----------------------------------------------------------------------------
template<bool ACC>
__global__ __launch_bounds__(256)
void bnrelu_out(const float4* __restrict__ raw, const float* __restrict__ scale,
                const float* __restrict__ shift, float4* __restrict__ out,
                int hw4, int C, long n4, int off, float* lacc)
{
    long i = (long)blockIdx.x * blockDim.x + threadIdx.x;
    float part = 0.f;
    for (; i < n4; i += (long)gridDim.x * blockDim.x) {
        int c = (int)((i / hw4) % C);
        float s = scale[off + c], sh = shift[off + c];
        float4 v = raw[i];
        v.x = fmaxf(fmaf(v.x, s, sh), 0.f);
        v.y = fmaxf(fmaf(v.y, s, sh), 0.f);
        v.z = fmaxf(fmaf(v.z, s, sh), 0.f);
        v.w = fmaxf(fmaf(v.w, s, sh), 0.f);
        out[i] = v;
        if (ACC) part += v.x + v.y + v.z + v.w;
    }
    if (ACC) atomic_block_sum(part, lacc);
}

// ----------------------------------------------------------------------------
// FUSED: BN+ReLU of S2 -> outS  +  l2 sum  +  softmax-entropy (l3).
// ----------------------------------------------------------------------------
__global__ __launch_bounds__(256)
void bn_s_entropy_fused(const float4* __restrict__ raw,
                        const float* __restrict__ scale,   // +O5 applied
                        const float* __restrict__ shift,
                        float4* __restrict__ outS,
                        float* l2acc, float* l3acc)
{
    extern __shared__ float s[];        // 12288 floats = 48 KB
    const int b = blockIdx.x, t = threadIdx.x;

    float l2part = 0.f;
    for (int i = t; i < 3072; i += 256) {
        int c = i >> 4;
        float sc = scale[c], sh = shift[c];
        float4 v = raw[(long)b * 3072 + i];
        v.x = fmaxf(fmaf(v.x, sc, sh), 0.f);
        v.y = fmaxf(fmaf(v.y, sc, sh), 0.f);
        v.z = fmaxf(fmaf(v.z, sc, sh), 0.f);
        v.w = fmaxf(fmaf(v.w, sc, sh), 0.f);
        outS[(long)b * 3072 + i] = v;
        *reinterpret_cast<float4*>(&s[i * 4]) = v;
        l2part += v.x + v.y + v.z + v.w;
    }
    __syncthreads();

    float l3part = 0.f;
    if (t < 192) {
        float m = s[t];
#pragma unroll
        for (int i = 1; i < 64; ++i) m = fmaxf(m, s[i * 192 + t]);
        float s1 = 0.f, s2 = 0.f;
#pragma unroll
        for (int i = 0; i < 64; ++i) {
            float u = s[i * 192 + t] - m;
            float e = expf(u);
            s1 += e; s2 += e * u;
        }
        l3part = logf(s1) - s2 / s1;
    }
    atomic_block_sum(l2part, l2acc);
    __syncthreads();
    atomic_block_sum(l3part, l3acc);
}

// ----------------------------------------------------------------------------
// per-sample conv_transpose2d(A[b], W=S[b], stride=2, pad=3) + sigmoid + l1
// (proven 256-thread version)
// ----------------------------------------------------------------------------
__global__ __launch_bounds__(256)
void recon_kernel(const float* __restrict__ x, const float* __restrict__ A,
                  const float* __restrict__ S, float* lacc)
{
    extern __shared__ float sm[];
    float* A_s = sm;                 // [64][16][20]  (ix offset +2, zero padded)
    float* W_s = sm + 64 * 16 * 20;  // [i][j][ky][par][q]  (kx = par + 2q)
    const int b = blockIdx.x, t = threadIdx.x;

    for (int idx = t; idx < 64 * 16 * 20; idx += 256) A_s[idx] = 0.f;
    __syncthreads();
    for (int idx = t; idx < 64 * 256; idx += 256) {
        int i = idx >> 8, p = idx & 255, iy = p >> 4, ix = p & 15;
        A_s[(i * 16 + iy) * 20 + ix + 2] = A[(long)b * 16384 + idx];
    }
    for (int idx = t; idx < 64 * 192; idx += 256) {
        int i = idx / 192, r = idx % 192, j = r >> 6, k = r & 63;
        int ky = k >> 3, kx = k & 7;
        W_s[((i * 3 + j) * 8 + ky) * 8 + (kx & 1) * 4 + (kx >> 1)] =
            S[(long)b * 12288 + idx];
    }
    __syncthreads();

    const int oy = t >> 3, g = t & 7;
    const int x0 = (g >> 1) * 8 + (g & 1);       // outputs ox = x0 + 2m
    const int oyp = oy + 3;
    const int kyp = oyp & 1;
    const int kxp = (x0 + 3) & 1;
    const int u0  = (x0 + 3 - kxp) >> 1;

    float acc[3][4];
#pragma unroll
    for (int j = 0; j < 3; ++j)
#pragma unroll
        for (int m = 0; m < 4; ++m) acc[j][m] = 0.f;

#pragma unroll
    for (int kk = 0; kk < 4; ++kk) {
        int ky = kyp + 2 * kk;
        int iy = (oyp - ky) >> 1;
        if (iy < 0 || iy > 15) continue;
        for (int i = 0; i < 64; ++i) {
            const float* ar = A_s + (i * 16 + iy) * 20 + (u0 - 1);  // av[d] -> ix=u0-3+d
            float av[7];
#pragma unroll
            for (int d = 0; d < 7; ++d) av[d] = ar[d];
            const float* wb = W_s + ((i * 3) * 8 + ky) * 8 + kxp * 4;
            float4 wv[3];
            wv[0] = *reinterpret_cast<const float4*>(wb);
            wv[1] = *reinterpret_cast<const float4*>(wb + 64);
            wv[2] = *reinterpret_cast<const float4*>(wb + 128);
#pragma unroll
            for (int j = 0; j < 3; ++j)
#pragma unroll
                for (int m = 0; m < 4; ++m) {
                    acc[j][m] = fmaf(wv[j].x, av[3 + m], acc[j][m]);
                    acc[j][m] = fmaf(wv[j].y, av[2 + m], acc[j][m]);
                    acc[j][m] = fmaf(wv[j].z, av[1 + m], acc[j][m]);
                    acc[j][m] = fmaf(wv[j].w, av[0 + m], acc[j][m]);
                }
        }
    }

    float part = 0.f;
#pragma unroll
    for (int j = 0; j < 3; ++j)
#pragma unroll
        for (int m = 0; m < 4; ++m) {
            int ox = x0 + 2 * m;
            float r  = 1.f / (1.f + expf(-acc[j][m]));
            float xv = x[((long)(b * 3 + j)) * 1024 + oy * 32 + ox];
            float sx = 1.f / (1.f + expf(-xv));
            float d = sx - r;
            part += d * d;
        }
    atomic_block_sum(part, lacc);
}

// ----------------------------------------------------------------------------
__global__ void write_losses(const float* loss, float* outL)
{
    outL[0] = 0.1f * loss[0] * (1.f / 3145728.f);    // l1
    outL[1] = 0.1f * loss[1] * (1.f / 12582912.f);   // l2
    outL[2] = 0.1f * loss[2] * (1.f / 12582912.f);   // l3
}

// ============================================================================
extern "C" void kernel_launch(void* const* d_in, const int* in_sizes, int n_in,
                              void* d_out, int out_size)
{
    const float* x   = (const float*)d_in[0];
    const float* w1  = (const float*)d_in[1];
    const float* w2  = (const float*)d_in[2];
    const float* w3  = (const float*)d_in[3];
    const float* wa  = (const float*)d_in[4];
    const float* ws1 = (const float*)d_in[5];
    const float* ws2 = (const float*)d_in[6];
    const float* gam[6]; const float* bet[6];
    for (int i = 0; i < 6; ++i) {
        gam[i] = (const float*)d_in[7 + 2 * i];
        bet[i] = (const float*)d_in[8 + 2 * i];
    }

    float* outA = (float*)d_out;                           // [1024,64,16,16]
    float* outS = outA + (size_t)1024 * 64 * 256;          // [1024,192,8,8]
    float* outL = outA + (size_t)29360128;                 // 3 scalars

    float *h1, *h2, *AS, *S1, *S2, *Araw, *sum, *sq, *scale, *shift, *loss;
    cudaGetSymbolAddress((void**)&h1,    g_h1);
    cudaGetSymbolAddress((void**)&h2,    g_h2);
    cudaGetSymbolAddress((void**)&AS,    g_AS);
    cudaGetSymbolAddress((void**)&S1,    g_S1);
    cudaGetSymbolAddress((void**)&S2,    g_S2);
    cudaGetSymbolAddress((void**)&Araw,  g_Araw);
    cudaGetSymbolAddress((void**)&sum,   g_sum);
    cudaGetSymbolAddress((void**)&sq,    g_sq);
    cudaGetSymbolAddress((void**)&scale, g_scale);
    cudaGetSymbolAddress((void**)&shift, g_shift);
    cudaGetSymbolAddress((void**)&loss,  g_loss);

    // smem sizes
    const int SM1  = (3  * 18 * 36 + 3  * 9 * 16) * 4;  // 9504
    const int SM2  = (16 * 10 * 36 + 16 * 9 * 32) * 4;  // 41472  (COUTG=32, Y=4)
    const int SM3  = (8  * 17 * 36 + 8  * 9 * 64) * 4;  // 38016
    const int SMS1 = (16 * 10 * 20 + 16 * 9 * 64) * 4;  // 49664  (COUTG=64, Y=2)
    const int SMS2 = (8  * 17 * 20 + 8  * 9 * 96) * 4;  // 38528
    const int SMF  = 12288 * 4;                         // 49152
    const int SMR  = (64 * 16 * 20 + 64 * 192) * 4;     // 131072

    cudaFuncSetAttribute((const void*)conv3x3_v5<32,16,32,32,1,16,4,4,true>,
                         cudaFuncAttributeMaxDynamicSharedMemorySize, SM2);
    cudaFuncSetAttribute((const void*)conv3x3_v5<64,8,32,32,2,16,4,2,true>,
                         cudaFuncAttributeMaxDynamicSharedMemorySize, SM3);
    cudaFuncSetAttribute((const void*)conv3x3_v5<32,16,16,16,1,16,4,2,true>,
                         cudaFuncAttributeMaxDynamicSharedMemorySize, SMS1);
    cudaFuncSetAttribute((const void*)conv3x3_v5<192,8,16,16,2,12,4,1,true>,
                         cudaFuncAttributeMaxDynamicSharedMemorySize, SMS2);
    cudaFuncSetAttribute((const void*)bn_s_entropy_fused,
                         cudaFuncAttributeMaxDynamicSharedMemorySize, SMF);
    cudaFuncSetAttribute((const void*)recon_kernel,
                         cudaFuncAttributeMaxDynamicSharedMemorySize, SMR);

    zero_kernel<<<3, 256>>>(sum, sq, loss);

    // stage 0: conv1 3->32 @32x32
    conv3x3_v5<3,3,32,32,1,16,4,2,false><<<dim3(BATCH, 2, 2), 128, SM1>>>(
        x, 3, 0, nullptr, nullptr, w1, 32, h1, sum, sq, O0);
    bn_finalize<<<1, 32>>>(sum, sq, gam[0], bet[0], scale, shift,
                           1.f / 1048576.f, O0, 32);

    // stage 1: conv2 32->64 @32x32  (COUTG=32, CSPLIT=2, Y=4)
    conv3x3_v5<32,16,32,32,1,16,4,4,true><<<dim3(BATCH, 2, 4), 128, SM2>>>(
        h1, 32, 0, scale + O0, shift + O0, w2, 64, h2, sum, sq, O1);
    bn_finalize<<<1, 64>>>(sum, sq, gam[1], bet[1], scale, shift,
                           1.f / 1048576.f, O1, 64);

    // stage 2: conv3 64->64 stride2 -> 16x16
    conv3x3_v5<64,8,32,32,2,16,4,2,true><<<dim3(BATCH, 1, 2), 128, SM3>>>(
        h2, 64, 0, scale + O1, shift + O1, w3, 64, AS, sum, sq, O2);
    bn_finalize<<<1, 64>>>(sum, sq, gam[2], bet[2], scale, shift,
                           1.f / 262144.f, O2, 64);

    // stage 3: convA 1x1 (AS[:, :32]) -> 64ch @16x16
    conv1x1_bn<<<BATCH, 256>>>(AS, scale + O2, shift + O2, wa, Araw,
                               sum, sq, O3);
    bn_finalize<<<1, 64>>>(sum, sq, gam[3], bet[3], scale, shift,
                           1.f / 262144.f, O3, 64);

    // stage 4: convS1 (AS[:, 32:]) 32->192 @16x16  (COUTG=64, CSPLIT=4, Y=2)
    conv3x3_v5<32,16,16,16,1,16,4,2,true><<<dim3(BATCH, 3, 2), 128, SMS1>>>(
        AS, 64, 32, scale + O2, shift + O2, ws1, 192, S1, sum, sq, O4);
    bn_finalize<<<1, 192>>>(sum, sq, gam[4], bet[4], scale, shift,
                            1.f / 262144.f, O4, 192);

    // stage 5: convS2 192->192 stride2 -> 8x8
    conv3x3_v5<192,8,16,16,2,12,4,1,true><<<dim3(BATCH, 2, 1), 128, SMS2>>>(
        S1, 192, 0, scale + O4, shift + O4, ws2, 192, S2, sum, sq, O5);
    bn_finalize<<<1, 192>>>(sum, sq, gam[5], bet[5], scale, shift,
                            1.f / 65536.f, O5, 192);

    // materialize outputs
    bnrelu_out<false><<<1024, 256>>>((const float4*)Araw, scale, shift,
                                     (float4*)outA, 64, 64,
                                     (long)1024 * 64 * 64, O3, nullptr);
    bn_s_entropy_fused<<<BATCH, 256, SMF>>>((const float4*)S2,
                                            scale + O5, shift + O5,
                                            (float4*)outS, loss + 1, loss + 2);

    // losses
    recon_kernel<<<BATCH, 256, SMR>>>(x, outA, outS, loss + 0);
    write_losses<<<1, 1>>>(loss, outL);
}

// round 16
// speedup vs baseline: 1.0735x; 1.0735x over previous
#include <cuda_runtime.h>
#include <math.h>

#define BATCH 1024
typedef unsigned long long u64;

// ---------------- f32x2 packed-math helpers (sm_100+) ------------------------
__device__ __forceinline__ u64 splat2(float v) {
    u64 r;
    asm("mov.b64 %0, {%1, %1};" : "=l"(r) : "f"(v));
    return r;
}
__device__ __forceinline__ void fma2(u64& d, u64 a, u64 b) {
    asm("fma.rn.f32x2 %0, %1, %2, %0;" : "+l"(d) : "l"(a), "l"(b));
}
__device__ __forceinline__ float2 unpack2(u64 v) {
    float2 f;
    asm("mov.b64 {%0, %1}, %2;" : "=f"(f.x), "=f"(f.y) : "l"(v));
    return f;
}

// ---------------- device scratch (allocation-free rule: __device__ globals) --
__device__ float g_h1[(size_t)1024*32*32*32];   // conv1 raw out
__device__ float g_h2[(size_t)1024*64*32*32];   // conv2 raw out
__device__ float g_AS[(size_t)1024*64*16*16];   // conv3 raw out
__device__ float g_S1[(size_t)1024*192*16*16];  // convS1 raw out
__device__ float g_S2[(size_t)1024*192*8*8];    // convS2 raw out
__device__ float g_Araw[(size_t)1024*64*16*16]; // convA raw out

__device__ float g_sum[640];
__device__ float g_sq[640];
__device__ float g_scale[640];
__device__ float g_shift[640];
__device__ float g_loss[4];     // [0]=l1 sum, [1]=l2 sum, [2]=l3 sum

// stage channel offsets into stat arrays
#define O0 0     // 32 ch (conv1)
#define O1 32    // 64 ch (conv2)
#define O2 96    // 64 ch (conv3)
#define O3 160   // 64 ch (convA)
#define O4 224   // 192 ch (convS1)
#define O5 416   // 192 ch (convS2)

// ----------------------------------------------------------------------------
__global__ void zero_kernel(float* sum, float* sq, float* loss) {
    int i = blockIdx.x * blockDim.x + threadIdx.x;
    if (i < 608) { sum[i] = 0.f; sq[i] = 0.f; }
    if (i < 3) loss[i] = 0.f;
}

__device__ __forceinline__ void atomic_block_sum(float v, float* dst) {
    __shared__ float red[32];
    int lane = threadIdx.x & 31, warp = threadIdx.x >> 5;
#pragma unroll
    for (int o = 16; o > 0; o >>= 1) v += __shfl_xor_sync(0xffffffffu, v, o);
    if (lane == 0) red[warp] = v;
    __syncthreads();
    if (warp == 0) {
        int nw = (blockDim.x + 31) >> 5;
        float s = (lane < nw) ? red[lane] : 0.f;
#pragma unroll
        for (int o = 16; o > 0; o >>= 1) s += __shfl_xor_sync(0xffffffffu, s, o);
        if (lane == 0) atomicAdd(dst, s);
    }
}

// ----------------------------------------------------------------------------
// Direct 3x3 conv, pad=1, stride 1 or 2.  v5: 128-thread blocks, 4 blocks/SM,
// CPT output channels per thread (f32x2-packed pairs), PXPT consecutive x
// pixels per thread fed by aligned float4 windows per (c,ky), YSPLIT row
// splitting.  Generalized stats epilogue supports channel-sub groups smaller
// than a warp (SPAN = min(NPT,32)); PXPT in {2,4,8}.
// grid = (batch, COUT/COUTG, YSPLIT), 128 threads.
// ----------------------------------------------------------------------------
template<int CIN, int CSLAB, int HIN, int WIN, int STRIDE, int CPT, int PXPT,
         int YSPLIT, bool HASBN>
__global__ __launch_bounds__(128, 4)
void conv3x3_v5(const float* __restrict__ in, int cin_tot, int cin_off,
                const float* __restrict__ bscale, const float* __restrict__ bshift,
                const float* __restrict__ w, int cout_tot,
                float* __restrict__ out,
                float* __restrict__ chsum, float* __restrict__ chsq, int ch_off)
{
    constexpr int TPB    = 128;
    constexpr int HOUT   = (STRIDE == 1) ? HIN : HIN / 2;
    constexpr int WOUT   = (STRIDE == 1) ? WIN : WIN / 2;
    constexpr int HOB    = HOUT / YSPLIT;          // output rows per block
    constexpr int TPR    = WOUT / PXPT;            // threads per output row
    constexpr int NPT    = HOB * TPR;              // pixel-thread count
    constexpr int CSPLIT = TPB / NPT;              // channel groups of threads
    constexpr int COUTG  = CPT * CSPLIT;           // out channels per block
    constexpr int HSLAB  = (HOB - 1) * STRIDE + 3;
    constexpr int WP     = ((WIN + 2 + 3) / 4) * 4;  // padded row, 16B aligned
    constexpr int NSLAB  = CIN / CSLAB;
    constexpr int IW     = (PXPT - 1) * STRIDE + 3;  // input window width
    constexpr int NV4    = (IW + 3) / 4;             // float4 loads per window
    constexpr int NPAIR  = CPT / 2;
    constexpr int NPIX   = HOUT * WOUT;
    constexpr int SPAN   = (NPT < 32) ? NPT : 32;    // reduce span (lanes)
    constexpr int NGRP   = TPB / SPAN;               // reduce groups
    constexpr int GPC    = NGRP / CSPLIT;            // groups per channel-sub

    extern __shared__ float sm[];
    float* s_in = sm;                         // CSLAB * HSLAB * WP
    float* s_w  = sm + CSLAB * HSLAB * WP;    // [c][tap][COUTG]
    __shared__ float s_red[NGRP][2 * CPT];

    const int b    = blockIdx.x;
    const int cog  = blockIdx.y * COUTG;
    const int oy0  = blockIdx.z * HOB;
    const int t    = threadIdx.x;
    const int pt   = t % NPT;
    const int csub = t / NPT;
    const int row  = pt / TPR;                // block-local output row
    const int x0   = (pt % TPR) * PXPT;       // first output col
    const int ib   = x0 * STRIDE;             // slab col of kx=0 (4-aligned)
    const int gy0  = oy0 * STRIDE - 1;        // input row of slab row 0

    u64 acc[NPAIR][PXPT];
#pragma unroll
    for (int i = 0; i < NPAIR; ++i)
#pragma unroll
        for (int p = 0; p < PXPT; ++p) acc[i][p] = 0ull;

    for (int sl = 0; sl < NSLAB; ++sl) {
        const int cbase = sl * CSLAB;
        __syncthreads();
        // ---- input slab: one thread = one (c,y) row; coalesced float4 ----
        for (int ridx = t; ridx < CSLAB * HSLAB; ridx += TPB) {
            const int c  = ridx / HSLAB;
            const int y  = ridx - c * HSLAB;
            const int gy = gy0 + y;
            float* dst = s_in + ridx * WP;
            if ((unsigned)gy >= (unsigned)HIN) {
#pragma unroll
                for (int j = 0; j < WP; ++j) dst[j] = 0.f;
            } else {
                const int gc = cin_off + cbase + c;
                const float4* src = reinterpret_cast<const float4*>(
                    in + (((long)(b * cin_tot + gc)) * HIN + gy) * WIN);
                dst[0] = 0.f;
#pragma unroll
                for (int j = WIN + 1; j < WP; ++j) dst[j] = 0.f;
                if (HASBN) {
                    const float sc = bscale[gc], sh = bshift[gc];
#pragma unroll
                    for (int j = 0; j < WIN / 4; ++j) {
                        float4 v = src[j];
                        dst[1 + 4*j + 0] = fmaxf(fmaf(v.x, sc, sh), 0.f);
                        dst[1 + 4*j + 1] = fmaxf(fmaf(v.y, sc, sh), 0.f);
                        dst[1 + 4*j + 2] = fmaxf(fmaf(v.z, sc, sh), 0.f);
                        dst[1 + 4*j + 3] = fmaxf(fmaf(v.w, sc, sh), 0.f);
                    }
                } else {
#pragma unroll
                    for (int j = 0; j < WIN / 4; ++j) {
                        float4 v = src[j];
                        dst[1 + 4*j + 0] = v.x;
                        dst[1 + 4*j + 1] = v.y;
                        dst[1 + 4*j + 2] = v.z;
                        dst[1 + 4*j + 3] = v.w;
                    }
                }
            }
        }
        // ---- weights: s_w[(c*9+tap)*COUTG + co] ----
        for (int idx = t; idx < CSLAB * 9 * COUTG; idx += TPB) {
            int co  = idx % COUTG;
            int r   = idx / COUTG;
            int tap = r % 9;
            int c   = r / 9;
            s_w[idx] = w[((long)(cog + co) * CIN + cbase + c) * 9 + tap];
        }
        __syncthreads();
        // ---- compute (unroll 2 across channels for latency overlap) ----
#pragma unroll 2
        for (int c = 0; c < CSLAB; ++c) {
            const float* si = s_in + (c * HSLAB + row * STRIDE) * WP + ib;
#pragma unroll
            for (int ky = 0; ky < 3; ++ky) {
                float4 v4[NV4];
                const float4* rp = reinterpret_cast<const float4*>(si + ky * WP);
#pragma unroll
                for (int j = 0; j < NV4; ++j) v4[j] = rp[j];
                const float* vf = reinterpret_cast<const float*>(v4);
                u64 iv[IW];
#pragma unroll
                for (int d = 0; d < IW; ++d) iv[d] = splat2(vf[d]);
#pragma unroll
                for (int kx = 0; kx < 3; ++kx) {
                    const ulonglong2* wr = reinterpret_cast<const ulonglong2*>(
                        s_w + (c * 9 + ky * 3 + kx) * COUTG + csub * CPT);
#pragma unroll
                    for (int q = 0; q < CPT / 4; ++q) {
                        ulonglong2 wp = wr[q];
#pragma unroll
                        for (int p = 0; p < PXPT; ++p) {
                            fma2(acc[2*q  ][p], wp.x, iv[p * STRIDE + kx]);
                            fma2(acc[2*q+1][p], wp.y, iv[p * STRIDE + kx]);
                        }
                    }
                }
            }
        }
    }

    // ---- epilogue: vectorized raw out + per-channel stats ----
    const int lane = t & 31;
    const int grp  = t / SPAN;
    const long obase = ((long)b * cout_tot + cog + csub * CPT) * NPIX
                       + (oy0 + row) * WOUT + x0;
#pragma unroll
    for (int pr = 0; pr < NPAIR; ++pr) {
        float vx[PXPT], vy[PXPT];
        float psA = 0.f, pqA = 0.f, psB = 0.f, pqB = 0.f;
#pragma unroll
        for (int p = 0; p < PXPT; ++p) {
            float2 v = unpack2(acc[pr][p]);
            vx[p] = v.x; vy[p] = v.y;
            psA += v.x; pqA += v.x * v.x;
            psB += v.y; pqB += v.y * v.y;
        }
        if constexpr (PXPT >= 4) {
#pragma unroll
            for (int q4 = 0; q4 < PXPT / 4; ++q4) {
                *reinterpret_cast<float4*>(out + obase + (long)(2*pr) * NPIX + 4*q4) =
                    make_float4(vx[4*q4], vx[4*q4+1], vx[4*q4+2], vx[4*q4+3]);
                *reinterpret_cast<float4*>(out + obase + (long)(2*pr+1) * NPIX + 4*q4) =
                    make_float4(vy[4*q4], vy[4*q4+1], vy[4*q4+2], vy[4*q4+3]);
            }
        } else {
            *reinterpret_cast<float2*>(out + obase + (long)(2*pr) * NPIX) =
                make_float2(vx[0], vx[1]);
            *reinterpret_cast<float2*>(out + obase + (long)(2*pr+1) * NPIX) =
                make_float2(vy[0], vy[1]);
        }
#pragma unroll
        for (int o = SPAN / 2; o > 0; o >>= 1) {
            psA += __shfl_xor_sync(0xffffffffu, psA, o);
            pqA += __shfl_xor_sync(0xffffffffu, pqA, o);
            psB += __shfl_xor_sync(0xffffffffu, psB, o);
            pqB += __shfl_xor_sync(0xffffffffu, pqB, o);
        }
        if ((lane % SPAN) == 0) {
            s_red[grp][4*pr]   = psA; s_red[grp][4*pr+1] = pqA;
            s_red[grp][4*pr+2] = psB; s_red[grp][4*pr+3] = pqB;
        }
    }
    __syncthreads();
    if (t < COUTG) {
        const int sub = t / CPT, co = t % CPT;
        float ps = 0.f, pq = 0.f;
#pragma unroll
        for (int gi = 0; gi < GPC; ++gi) {
            ps += s_red[sub * GPC + gi][2*co];
            pq += s_red[sub * GPC + gi][2*co+1];
        }
        atomicAdd(&chsum[ch_off + cog + t], ps);
        atomicAdd(&chsq [ch_off + cog + t], pq);
    }
}

// ----------------------------------------------------------------------------
// 1x1 conv (A head): AS[:, :32] -> 64 channels over 16x16, f32x2 packed
// ----------------------------------------------------------------------------
__global__ __launch_bounds__(256)
void conv1x1_bn(const float* __restrict__ in, const float* __restrict__ bscale,
                const float* __restrict__ bshift, const float* __restrict__ w,
                float* __restrict__ out,
                float* __restrict__ chsum, float* __restrict__ chsq, int ch_off)
{
    __shared__ __align__(16) float s_in[32 * 256];
    __shared__ __align__(16) float s_w[32 * 64];
    __shared__ float s_red[8][128];
    const int b = blockIdx.x, t = threadIdx.x;

    for (int idx = t; idx < 32 * 256; idx += 256) {
        int ci = idx >> 8, p = idx & 255;
        float v = in[((long)(b * 64 + ci)) * 256 + p];
        s_in[idx] = fmaxf(fmaf(v, bscale[ci], bshift[ci]), 0.f);
    }
    for (int idx = t; idx < 32 * 64; idx += 256) {
        int ci = idx >> 6, co = idx & 63;
        s_w[idx] = w[co * 32 + ci];
    }
    __syncthreads();

    u64 acc[32];
#pragma unroll
    for (int i = 0; i < 32; ++i) acc[i] = 0ull;

    for (int ci = 0; ci < 32; ++ci) {
        u64 vp = splat2(s_in[ci * 256 + t]);
        const ulonglong2* wr = reinterpret_cast<const ulonglong2*>(s_w + ci * 64);
#pragma unroll
        for (int q = 0; q < 16; ++q) {
            ulonglong2 wp = wr[q];
            fma2(acc[2*q  ], wp.x, vp);
            fma2(acc[2*q+1], wp.y, vp);
        }
    }

    const int lane = t & 31, warp = t >> 5;
#pragma unroll
    for (int p = 0; p < 32; ++p) {
        float2 v = unpack2(acc[p]);
        out[((long)(b * 64 + 2*p    )) * 256 + t] = v.x;
        out[((long)(b * 64 + 2*p + 1)) * 256 + t] = v.y;
        float psA = v.x, pqA = v.x * v.x, psB = v.y, pqB = v.y * v.y;
#pragma unroll
        for (int o = 16; o > 0; o >>= 1) {
            psA += __shfl_xor_sync(0xffffffffu, psA, o);
            pqA += __shfl_xor_sync(0xffffffffu, pqA, o);
            psB += __shfl_xor_sync(0xffffffffu, psB, o);
            pqB += __shfl_xor_sync(0xffffffffu, pqB, o);
        }
        if (lane == 0) {
            s_red[warp][4*p]   = psA; s_red[warp][4*p+1] = pqA;
            s_red[warp][4*p+2] = psB; s_red[warp][4*p+3] = pqB;
        }
    }
    __syncthreads();
    if (t < 64) {
        float ps = 0.f, pq = 0.f;
#pragma unroll
        for (int wi = 0; wi < 8; ++wi) { ps += s_red[wi][2*t]; pq += s_red[wi][2*t+1]; }
        atomicAdd(&chsum[ch_off + t], ps);
        atomicAdd(&chsq [ch_off + t], pq);
    }
}

// ----------------------------------------------------------------------------
__global__ void bn_finalize(const float* __restrict__ sum, const float* __restrict__ sq,
                            const float* __restrict__ g, const float* __restrict__ bb,
                            float* __restrict__ scale, float* __restrict__ shift,
                            float inv_n, int off, int C)
{
    int c = threadIdx.x;
    if (c >= C) return;
    float m   = sum[off + c] * inv_n;
    float var = sq[off + c] * inv_n - m * m;
    float s   = g[c] * rsqrtf(var + 1e-5f);
    scale[off + c] = s;
    shift[off + c] = bb[c] - m * s;
}

// ----------------------------------------------------------------------------
template<bool ACC>
__global__ __launch_bounds__(256)
void bnrelu_out(const float4* __restrict__ raw, const float* __restrict__ scale,
                const float* __restrict__ shift, float4* __restrict__ out,
                int hw4, int C, long n4, int off, float* lacc)
{
    long i = (long)blockIdx.x * blockDim.x + threadIdx.x;
    float part = 0.f;
    for (; i < n4; i += (long)gridDim.x * blockDim.x) {
        int c = (int)((i / hw4) % C);
        float s = scale[off + c], sh = shift[off + c];
        float4 v = raw[i];
        v.x = fmaxf(fmaf(v.x, s, sh), 0.f);
        v.y = fmaxf(fmaf(v.y, s, sh), 0.f);
        v.z = fmaxf(fmaf(v.z, s, sh), 0.f);
        v.w = fmaxf(fmaf(v.w, s, sh), 0.f);
        out[i] = v;
        if (ACC) part += v.x + v.y + v.z + v.w;
    }
    if (ACC) atomic_block_sum(part, lacc);
}

// ----------------------------------------------------------------------------
// FUSED: BN+ReLU of S2 -> outS  +  l2 sum  +  softmax-entropy (l3).
// ----------------------------------------------------------------------------
__global__ __launch_bounds__(256)
void bn_s_entropy_fused(const float4* __restrict__ raw,
                        const float* __restrict__ scale,   // +O5 applied
                        const float* __restrict__ shift,
                        float4* __restrict__ outS,
                        float* l2acc, float* l3acc)
{
    extern __shared__ float s[];        // 12288 floats = 48 KB
    const int b = blockIdx.x, t = threadIdx.x;

    float l2part = 0.f;
    for (int i = t; i < 3072; i += 256) {
        int c = i >> 4;
        float sc = scale[c], sh = shift[c];
        float4 v = raw[(long)b * 3072 + i];
        v.x = fmaxf(fmaf(v.x, sc, sh), 0.f);
        v.y = fmaxf(fmaf(v.y, sc, sh), 0.f);
        v.z = fmaxf(fmaf(v.z, sc, sh), 0.f);
        v.w = fmaxf(fmaf(v.w, sc, sh), 0.f);
        outS[(long)b * 3072 + i] = v;
        *reinterpret_cast<float4*>(&s[i * 4]) = v;
        l2part += v.x + v.y + v.z + v.w;
    }
    __syncthreads();

    float l3part = 0.f;
    if (t < 192) {
        float m = s[t];
#pragma unroll
        for (int i = 1; i < 64; ++i) m = fmaxf(m, s[i * 192 + t]);
        float s1 = 0.f, s2 = 0.f;
#pragma unroll
        for (int i = 0; i < 64; ++i) {
            float u = s[i * 192 + t] - m;
            float e = expf(u);
            s1 += e; s2 += e * u;
        }
        l3part = logf(s1) - s2 / s1;
    }
    atomic_block_sum(l2part, l2acc);
    __syncthreads();
    atomic_block_sum(l3part, l3acc);
}

// ----------------------------------------------------------------------------
// per-sample conv_transpose2d(A[b], W=S[b], stride=2, pad=3) + sigmoid + l1
// (proven 256-thread version)
// ----------------------------------------------------------------------------
__global__ __launch_bounds__(256)
void recon_kernel(const float* __restrict__ x, const float* __restrict__ A,
                  const float* __restrict__ S, float* lacc)
{
    extern __shared__ float sm[];
    float* A_s = sm;                 // [64][16][20]  (ix offset +2, zero padded)
    float* W_s = sm + 64 * 16 * 20;  // [i][j][ky][par][q]  (kx = par + 2q)
    const int b = blockIdx.x, t = threadIdx.x;

    for (int idx = t; idx < 64 * 16 * 20; idx += 256) A_s[idx] = 0.f;
    __syncthreads();
    for (int idx = t; idx < 64 * 256; idx += 256) {
        int i = idx >> 8, p = idx & 255, iy = p >> 4, ix = p & 15;
        A_s[(i * 16 + iy) * 20 + ix + 2] = A[(long)b * 16384 + idx];
    }
    for (int idx = t; idx < 64 * 192; idx += 256) {
        int i = idx / 192, r = idx % 192, j = r >> 6, k = r & 63;
        int ky = k >> 3, kx = k & 7;
        W_s[((i * 3 + j) * 8 + ky) * 8 + (kx & 1) * 4 + (kx >> 1)] =
            S[(long)b * 12288 + idx];
    }
    __syncthreads();

    const int oy = t >> 3, g = t & 7;
    const int x0 = (g >> 1) * 8 + (g & 1);       // outputs ox = x0 + 2m
    const int oyp = oy + 3;
    const int kyp = oyp & 1;
    const int kxp = (x0 + 3) & 1;
    const int u0  = (x0 + 3 - kxp) >> 1;

    float acc[3][4];
#pragma unroll
    for (int j = 0; j < 3; ++j)
#pragma unroll
        for (int m = 0; m < 4; ++m) acc[j][m] = 0.f;

#pragma unroll
    for (int kk = 0; kk < 4; ++kk) {
        int ky = kyp + 2 * kk;
        int iy = (oyp - ky) >> 1;
        if (iy < 0 || iy > 15) continue;
        for (int i = 0; i < 64; ++i) {
            const float* ar = A_s + (i * 16 + iy) * 20 + (u0 - 1);  // av[d] -> ix=u0-3+d
            float av[7];
#pragma unroll
            for (int d = 0; d < 7; ++d) av[d] = ar[d];
            const float* wb = W_s + ((i * 3) * 8 + ky) * 8 + kxp * 4;
            float4 wv[3];
            wv[0] = *reinterpret_cast<const float4*>(wb);
            wv[1] = *reinterpret_cast<const float4*>(wb + 64);
            wv[2] = *reinterpret_cast<const float4*>(wb + 128);
#pragma unroll
            for (int j = 0; j < 3; ++j)
#pragma unroll
                for (int m = 0; m < 4; ++m) {
                    acc[j][m] = fmaf(wv[j].x, av[3 + m], acc[j][m]);
                    acc[j][m] = fmaf(wv[j].y, av[2 + m], acc[j][m]);
                    acc[j][m] = fmaf(wv[j].z, av[1 + m], acc[j][m]);
                    acc[j][m] = fmaf(wv[j].w, av[0 + m], acc[j][m]);
                }
        }
    }

    float part = 0.f;
#pragma unroll
    for (int j = 0; j < 3; ++j)
#pragma unroll
        for (int m = 0; m < 4; ++m) {
            int ox = x0 + 2 * m;
            float r  = 1.f / (1.f + expf(-acc[j][m]));
            float xv = x[((long)(b * 3 + j)) * 1024 + oy * 32 + ox];
            float sx = 1.f / (1.f + expf(-xv));
            float d = sx - r;
            part += d * d;
        }
    atomic_block_sum(part, lacc);
}

// ----------------------------------------------------------------------------
__global__ void write_losses(const float* loss, float* outL)
{
    outL[0] = 0.1f * loss[0] * (1.f / 3145728.f);    // l1
    outL[1] = 0.1f * loss[1] * (1.f / 12582912.f);   // l2
    outL[2] = 0.1f * loss[2] * (1.f / 12582912.f);   // l3
}

// ============================================================================
extern "C" void kernel_launch(void* const* d_in, const int* in_sizes, int n_in,
                              void* d_out, int out_size)
{
    const float* x   = (const float*)d_in[0];
    const float* w1  = (const float*)d_in[1];
    const float* w2  = (const float*)d_in[2];
    const float* w3  = (const float*)d_in[3];
    const float* wa  = (const float*)d_in[4];
    const float* ws1 = (const float*)d_in[5];
    const float* ws2 = (const float*)d_in[6];
    const float* gam[6]; const float* bet[6];
    for (int i = 0; i < 6; ++i) {
        gam[i] = (const float*)d_in[7 + 2 * i];
        bet[i] = (const float*)d_in[8 + 2 * i];
    }

    float* outA = (float*)d_out;                           // [1024,64,16,16]
    float* outS = outA + (size_t)1024 * 64 * 256;          // [1024,192,8,8]
    float* outL = outA + (size_t)29360128;                 // 3 scalars

    float *h1, *h2, *AS, *S1, *S2, *Araw, *sum, *sq, *scale, *shift, *loss;
    cudaGetSymbolAddress((void**)&h1,    g_h1);
    cudaGetSymbolAddress((void**)&h2,    g_h2);
    cudaGetSymbolAddress((void**)&AS,    g_AS);
    cudaGetSymbolAddress((void**)&S1,    g_S1);
    cudaGetSymbolAddress((void**)&S2,    g_S2);
    cudaGetSymbolAddress((void**)&Araw,  g_Araw);
    cudaGetSymbolAddress((void**)&sum,   g_sum);
    cudaGetSymbolAddress((void**)&sq,    g_sq);
    cudaGetSymbolAddress((void**)&scale, g_scale);
    cudaGetSymbolAddress((void**)&shift, g_shift);
    cudaGetSymbolAddress((void**)&loss,  g_loss);

    // smem sizes
    const int SM1  = (3  * 18 * 36 + 3  * 9 * 16) * 4;  // 9504
    const int SM2  = (16 * 18 * 36 + 16 * 9 * 16) * 4;  // 50688  (CPT=8,PXPT=8,Y=2)
    const int SM3  = (8  * 17 * 36 + 8  * 9 * 64) * 4;  // 38016
    const int SMS1 = (16 * 18 * 20 + 16 * 9 * 32) * 4;  // 41472  (CPT=8,PXPT=8,Y=1)
    const int SMS2 = (8  * 17 * 20 + 8  * 9 * 96) * 4;  // 38528
    const int SMF  = 12288 * 4;                         // 49152
    const int SMR  = (64 * 16 * 20 + 64 * 192) * 4;     // 131072

    cudaFuncSetAttribute((const void*)conv3x3_v5<32,16,32,32,1,8,8,2,true>,
                         cudaFuncAttributeMaxDynamicSharedMemorySize, SM2);
    cudaFuncSetAttribute((const void*)conv3x3_v5<64,8,32,32,2,16,4,2,true>,
                         cudaFuncAttributeMaxDynamicSharedMemorySize, SM3);
    cudaFuncSetAttribute((const void*)conv3x3_v5<32,16,16,16,1,8,8,1,true>,
                         cudaFuncAttributeMaxDynamicSharedMemorySize, SMS1);
    cudaFuncSetAttribute((const void*)conv3x3_v5<192,8,16,16,2,12,4,1,true>,
                         cudaFuncAttributeMaxDynamicSharedMemorySize, SMS2);
    cudaFuncSetAttribute((const void*)bn_s_entropy_fused,
                         cudaFuncAttributeMaxDynamicSharedMemorySize, SMF);
    cudaFuncSetAttribute((const void*)recon_kernel,
                         cudaFuncAttributeMaxDynamicSharedMemorySize, SMR);

    zero_kernel<<<3, 256>>>(sum, sq, loss);

    // stage 0: conv1 3->32 @32x32
    conv3x3_v5<3,3,32,32,1,16,4,2,false><<<dim3(BATCH, 2, 2), 128, SM1>>>(
        x, 3, 0, nullptr, nullptr, w1, 32, h1, sum, sq, O0);
    bn_finalize<<<1, 32>>>(sum, sq, gam[0], bet[0], scale, shift,
                           1.f / 1048576.f, O0, 32);

    // stage 1: conv2 32->64 @32x32  (CPT=8, PXPT=8, COUTG=16, Y=2)
    conv3x3_v5<32,16,32,32,1,8,8,2,true><<<dim3(BATCH, 4, 2), 128, SM2>>>(
        h1, 32, 0, scale + O0, shift + O0, w2, 64, h2, sum, sq, O1);
    bn_finalize<<<1, 64>>>(sum, sq, gam[1], bet[1], scale, shift,
                           1.f / 1048576.f, O1, 64);

    // stage 2: conv3 64->64 stride2 -> 16x16
    conv3x3_v5<64,8,32,32,2,16,4,2,true><<<dim3(BATCH, 1, 2), 128, SM3>>>(
        h2, 64, 0, scale + O1, shift + O1, w3, 64, AS, sum, sq, O2);
    bn_finalize<<<1, 64>>>(sum, sq, gam[2], bet[2], scale, shift,
                           1.f / 262144.f, O2, 64);

    // stage 3: convA 1x1 (AS[:, :32]) -> 64ch @16x16
    conv1x1_bn<<<BATCH, 256>>>(AS, scale + O2, shift + O2, wa, Araw,
                               sum, sq, O3);
    bn_finalize<<<1, 64>>>(sum, sq, gam[3], bet[3], scale, shift,
                           1.f / 262144.f, O3, 64);

    // stage 4: convS1 (AS[:, 32:]) 32->192 @16x16  (CPT=8, PXPT=8, COUTG=32)
    conv3x3_v5<32,16,16,16,1,8,8,1,true><<<dim3(BATCH, 6, 1), 128, SMS1>>>(
        AS, 64, 32, scale + O2, shift + O2, ws1, 192, S1, sum, sq, O4);
    bn_finalize<<<1, 192>>>(sum, sq, gam[4], bet[4], scale, shift,
                            1.f / 262144.f, O4, 192);

    // stage 5: convS2 192->192 stride2 -> 8x8
    conv3x3_v5<192,8,16,16,2,12,4,1,true><<<dim3(BATCH, 2, 1), 128, SMS2>>>(
        S1, 192, 0, scale + O4, shift + O4, ws2, 192, S2, sum, sq, O5);
    bn_finalize<<<1, 192>>>(sum, sq, gam[5], bet[5], scale, shift,
                            1.f / 65536.f, O5, 192);

    // materialize outputs
    bnrelu_out<false><<<1024, 256>>>((const float4*)Araw, scale, shift,
                                     (float4*)outA, 64, 64,
                                     (long)1024 * 64 * 64, O3, nullptr);
    bn_s_entropy_fused<<<BATCH, 256, SMF>>>((const float4*)S2,
                                            scale + O5, shift + O5,
                                            (float4*)outS, loss + 1, loss + 2);

    // losses
    recon_kernel<<<BATCH, 256, SMR>>>(x, outA, outS, loss + 0);
    write_losses<<<1, 1>>>(loss, outL);
}